// round 7
// baseline (speedup 1.0000x reference)
#include <cuda_runtime.h>
#include <math.h>

// B=131072, D=512, N=1.
// loss_b = log1p(exp((dot(img,neg) - dot(img,pos)) / 50)); output = mean_b loss_b.
// Persistent main kernel (2048 blocks, 8 rows/warp) + tiny finalize over 2048 partials.

#define B_TOTAL 131072
#define D_F4 128              // 512 floats = 128 float4 per row
#define WARPS_PER_BLOCK 8
#define THREADS 256
#define NBLOCKS 2048
#define TOTAL_WARPS (NBLOCKS * WARPS_PER_BLOCK)        // 16384
#define ROWS_PER_WARP (B_TOTAL / TOTAL_WARPS)          // 8

__device__ __align__(16) float g_partial[NBLOCKS];

__global__ __launch_bounds__(THREADS) void loss_main_kernel(
    const float4* __restrict__ img,
    const float4* __restrict__ pos,
    const float4* __restrict__ neg)
{
    const int wid  = threadIdx.x >> 5;
    const int lane = threadIdx.x & 31;
    const size_t warp_g = (size_t)blockIdx.x * WARPS_PER_BLOCK + wid;

    float loss = 0.0f;

#pragma unroll
    for (int r = 0; r < ROWS_PER_WARP; r++) {
        const size_t row  = warp_g + (size_t)r * TOTAL_WARPS;
        const size_t base = row * D_F4 + lane;

        float dp = 0.0f, dn = 0.0f;
#pragma unroll
        for (int i = 0; i < 4; i++) {
            const float4 a = __ldg(img + base + i * 32);
            const float4 p = __ldg(pos + base + i * 32);
            const float4 n = __ldg(neg + base + i * 32);
            dp += a.x * p.x + a.y * p.y + a.z * p.z + a.w * p.w;
            dn += a.x * n.x + a.y * n.y + a.z * n.z + a.w * n.w;
        }

#pragma unroll
        for (int off = 16; off; off >>= 1) {
            dp += __shfl_xor_sync(0xffffffffu, dp, off);
            dn += __shfl_xor_sync(0xffffffffu, dn, off);
        }

        // -log(ep/(ep+en)) == log1p(exp((dn-dp)/50)); all lanes compute, lane0's value used
        loss += log1pf(expf((dn - dp) * 0.02f));
    }

    __shared__ float s_loss[WARPS_PER_BLOCK];
    if (lane == 0) s_loss[wid] = loss;
    __syncthreads();

    if (threadIdx.x == 0) {
        float sum = 0.0f;
#pragma unroll
        for (int i = 0; i < WARPS_PER_BLOCK; i++) sum += s_loss[i];
        g_partial[blockIdx.x] = sum;          // plain STG: no zero pass needed
    }
}

__global__ __launch_bounds__(THREADS) void finalize_kernel(float* __restrict__ out) {
    const int wid  = threadIdx.x >> 5;
    const int lane = threadIdx.x & 31;

    const float4* p4 = (const float4*)g_partial;   // 512 float4
    float acc = 0.0f;
#pragma unroll
    for (int i = 0; i < (NBLOCKS / 4) / THREADS; i++) {   // 2 iters
        float4 v = p4[threadIdx.x + i * THREADS];
        acc += v.x + v.y + v.z + v.w;
    }
#pragma unroll
    for (int off = 16; off; off >>= 1)
        acc += __shfl_xor_sync(0xffffffffu, acc, off);

    __shared__ float s_fin[WARPS_PER_BLOCK];
    if (lane == 0) s_fin[wid] = acc;
    __syncthreads();
    if (threadIdx.x == 0) {
        float tot = 0.0f;
#pragma unroll
        for (int i = 0; i < WARPS_PER_BLOCK; i++) tot += s_fin[i];
        out[0] = tot / (float)B_TOTAL;
    }
}

extern "C" void kernel_launch(void* const* d_in, const int* in_sizes, int n_in,
                              void* d_out, int out_size) {
    (void)in_sizes; (void)n_in; (void)out_size;
    const float4* img = (const float4*)d_in[0];
    const float4* pos = (const float4*)d_in[1];
    const float4* neg = (const float4*)d_in[2];
    float* out = (float*)d_out;

    loss_main_kernel<<<NBLOCKS, THREADS>>>(img, pos, neg);
    finalize_kernel<<<1, THREADS>>>(out);
}